// round 3
// baseline (speedup 1.0000x reference)
#include <cuda_runtime.h>
#include <cuda_bf16.h>

// Shapes (fixed by the problem)
#define B_  32
#define N_  8
#define LQ_ 256
#define LD_ 512
#define D_  768

#define D4_      (D_ / 4)              // 192 float4 per row
#define TOTAL4_  (B_ * N_ * LD_ * D4_) // 25,165,824 float4 in docs
#define BN_STRIDE4_ (LD_ * D4_)        // float4 per (b,n) slab = 98304

// Scratch (no cudaMalloc allowed)
__device__ float4 g_qsum4[B_ * D4_];   // qsum[b][d], as float4
__device__ float  g_sign[B_ * N_];     // +1 / -1 per (b,n)
__device__ double g_acc;

// ---------------------------------------------------------------------------
// Pass 0: decode is_ans (dtype delivered by harness is unknown: int32,
// float32, or uint8). Sniff encoding from the first 256 bytes, which are
// in-bounds under every candidate encoding. Also zero the accumulator.
// ---------------------------------------------------------------------------
__global__ void decode_sign_kernel(const unsigned char* __restrict__ p) {
    __shared__ int enc;   // 0 = int32, 1 = float32, 2 = uint8
    if (threadIdx.x == 0) {
        const unsigned int* w = (const unsigned int*)p;
        bool all01 = true, allf = true;
        for (int i = 0; i < (B_ * N_) / 4; ++i) {   // 64 words = 256 bytes
            unsigned int v = w[i];
            if (v != 0u && v != 1u)           all01 = false;
            if (v != 0u && v != 0x3F800000u)  allf  = false;
        }
        enc = all01 ? 0 : (allf ? 1 : 2);
        g_acc = 0.0;
    }
    __syncthreads();
    int i = threadIdx.x;                 // 0 .. 255
    bool ans;
    if (enc == 0)      ans = ((const int*)p)[i]   != 0;
    else if (enc == 1) ans = ((const float*)p)[i] != 0.0f;
    else               ans = p[i]                 != 0;
    g_sign[i] = ans ? -1.0f : 1.0f;
}

// ---------------------------------------------------------------------------
// Pass 1: qsum[b,d] = sum_l questions[b,l,d].  One thread per (b,d).
// ---------------------------------------------------------------------------
__global__ void qsum_kernel(const float* __restrict__ q) {
    int gid = blockIdx.x * blockDim.x + threadIdx.x;   // 0 .. B*D-1
    if (gid >= B_ * D_) return;
    int b = gid / D_;
    int d = gid - b * D_;

    const float* p = q + (size_t)b * LQ_ * D_ + d;
    float s = 0.f;
#pragma unroll 8
    for (int l = 0; l < LQ_; ++l)
        s += p[(size_t)l * D_];
    reinterpret_cast<float*>(g_qsum4)[gid] = s;
}

// ---------------------------------------------------------------------------
// Pass 2: streaming reduce over docs (the 402 MB tensor).
// acc += sign[b,n] * dot(qsum[b, d..d+3], docs[b,n,m, d..d+3]) per float4.
// ---------------------------------------------------------------------------
__global__ void docs_reduce_kernel(const float4* __restrict__ docs) {
    float acc = 0.f;
    const int stride = gridDim.x * blockDim.x;
    for (int i = blockIdx.x * blockDim.x + threadIdx.x; i < TOTAL4_; i += stride) {
        int bn = i / BN_STRIDE4_;          // b*N + n
        int d4 = i % D4_;                  // float4 column index
        float4 v  = docs[i];
        float4 qv = g_qsum4[(bn >> 3) * D4_ + d4];
        float t = v.x * qv.x + v.y * qv.y + v.z * qv.z + v.w * qv.w;
        acc += t * g_sign[bn];
    }

    // warp reduce
#pragma unroll
    for (int o = 16; o > 0; o >>= 1)
        acc += __shfl_down_sync(0xFFFFFFFFu, acc, o);

    __shared__ float warp_sums[8];
    int lane = threadIdx.x & 31;
    int wid  = threadIdx.x >> 5;
    if (lane == 0) warp_sums[wid] = acc;
    __syncthreads();

    if (wid == 0) {
        float v = (lane < (blockDim.x >> 5)) ? warp_sums[lane] : 0.f;
#pragma unroll
        for (int o = 4; o > 0; o >>= 1)
            v += __shfl_down_sync(0xFFFFFFFFu, v, o);
        if (lane == 0)
            atomicAdd(&g_acc, (double)v);
    }
}

// ---------------------------------------------------------------------------
// Finalize: apply the 1/(Lq*Ld) mean scaling and write the scalar output.
// ---------------------------------------------------------------------------
__global__ void finalize_kernel(float* __restrict__ out) {
    out[0] = (float)(g_acc * (1.0 / ((double)LQ_ * (double)LD_)));
}

extern "C" void kernel_launch(void* const* d_in, const int* in_sizes, int n_in,
                              void* d_out, int out_size) {
    const float*         questions = (const float*)d_in[0];
    const float*         docs      = (const float*)d_in[1];
    const unsigned char* is_ans    = (const unsigned char*)d_in[2];
    float* out = (float*)d_out;
    (void)in_sizes; (void)n_in; (void)out_size;

    decode_sign_kernel<<<1, B_ * N_>>>(is_ans);

    // Pass 1: 32*768 = 24576 threads
    qsum_kernel<<<(B_ * D_ + 255) / 256, 256>>>(questions);

    // Pass 2: 8 blocks per SM on 148 SMs
    docs_reduce_kernel<<<1184, 256>>>((const float4*)docs);

    finalize_kernel<<<1, 1>>>(out);
}

// round 4
// speedup vs baseline: 1.2137x; 1.2137x over previous
#include <cuda_runtime.h>
#include <cuda_bf16.h>

// Shapes (fixed by the problem)
#define B_  32
#define N_  8
#define LQ_ 256
#define LD_ 512
#define D_  768

#define D4_      (D_ / 4)              // 192 float4 per row
#define TOTAL4_  (B_ * N_ * LD_ * D4_) // 25,165,824 float4 in docs
#define BN_STRIDE4_ (LD_ * D4_)        // float4 per (b,n) slab = 98304

#define GRID2_   1184                  // 8 blocks/SM * 148 SMs
#define BLK2_    256
#define STRIDE2_ (GRID2_ * BLK2_)      // 303,104

// Scratch (no cudaMalloc allowed)
__device__ float4 g_qsum4[B_ * D4_];   // qsum[b][d], as float4
__device__ float  g_sign[B_ * N_];     // +1 / -1 per (b,n)
__device__ double g_acc;
__device__ unsigned int g_ticket;

// ---------------------------------------------------------------------------
// Kernel A: decode is_ans -> g_sign (block 0), compute qsum (all blocks),
// and reset the accumulator + ticket for this launch (graph-replay safe).
// is_ans dtype is sniffed (int32 / float32 / uint8) from the first 256 bytes,
// which are in-bounds under every candidate encoding.
// ---------------------------------------------------------------------------
__global__ void prep_kernel(const float* __restrict__ q,
                            const unsigned char* __restrict__ isa) {
    if (blockIdx.x == 0) {
        __shared__ int enc;   // 0 = int32, 1 = float32, 2 = uint8
        if (threadIdx.x == 0) {
            const unsigned int* w = (const unsigned int*)isa;
            bool all01 = true, allf = true;
            for (int i = 0; i < (B_ * N_) / 4; ++i) {   // 64 words = 256 bytes
                unsigned int v = w[i];
                if (v != 0u && v != 1u)           all01 = false;
                if (v != 0u && v != 0x3F800000u)  allf  = false;
            }
            enc = all01 ? 0 : (allf ? 1 : 2);
            g_acc = 0.0;
            g_ticket = 0u;
        }
        __syncthreads();
        int i = threadIdx.x;                 // 0 .. 255
        bool ans;
        if (enc == 0)      ans = ((const int*)isa)[i]   != 0;
        else if (enc == 1) ans = ((const float*)isa)[i] != 0.0f;
        else               ans = isa[i]                 != 0;
        g_sign[i] = ans ? -1.0f : 1.0f;
    }

    // qsum[b,d] = sum_l questions[b,l,d]; one thread per (b,d)
    int gid = blockIdx.x * blockDim.x + threadIdx.x;   // 0 .. B*D-1
    if (gid >= B_ * D_) return;
    int b = gid / D_;
    int d = gid - b * D_;
    const float* p = q + (size_t)b * LQ_ * D_ + d;
    float s = 0.f;
#pragma unroll 8
    for (int l = 0; l < LQ_; ++l)
        s += p[(size_t)l * D_];
    reinterpret_cast<float*>(g_qsum4)[gid] = s;
}

// ---------------------------------------------------------------------------
// Kernel B: streaming reduce over docs (402 MB), 4-way unrolled so each
// thread keeps 4 independent LDG.128s in flight (MLP_p1 = 4). Last block
// out of the gate finalizes: scales by 1/(Lq*Ld) and writes the scalar.
// ---------------------------------------------------------------------------
__global__ void __launch_bounds__(BLK2_) docs_reduce_kernel(
        const float4* __restrict__ docs, float* __restrict__ out) {
    float acc = 0.f;
    int i0 = blockIdx.x * BLK2_ + threadIdx.x;

    for (; i0 < TOTAL4_; i0 += 4 * STRIDE2_) {
        float4 v[4];
        int    idx[4];
        bool   ok[4];
#pragma unroll
        for (int j = 0; j < 4; ++j) {
            idx[j] = i0 + j * STRIDE2_;
            ok[j]  = idx[j] < TOTAL4_;
            if (ok[j]) v[j] = __ldcs(&docs[idx[j]]);     // evict-first stream
        }
#pragma unroll
        for (int j = 0; j < 4; ++j) {
            if (ok[j]) {
                int bn = idx[j] / BN_STRIDE4_;           // b*N + n
                int d4 = idx[j] % D4_;
                float4 qv = g_qsum4[(bn >> 3) * D4_ + d4];
                float t = v[j].x * qv.x + v[j].y * qv.y
                        + v[j].z * qv.z + v[j].w * qv.w;
                acc += t * g_sign[bn];
            }
        }
    }

    // warp reduce
#pragma unroll
    for (int o = 16; o > 0; o >>= 1)
        acc += __shfl_down_sync(0xFFFFFFFFu, acc, o);

    __shared__ float warp_sums[BLK2_ / 32];
    int lane = threadIdx.x & 31;
    int wid  = threadIdx.x >> 5;
    if (lane == 0) warp_sums[wid] = acc;
    __syncthreads();

    __shared__ bool s_last;
    if (wid == 0) {
        float v = (lane < (BLK2_ / 32)) ? warp_sums[lane] : 0.f;
#pragma unroll
        for (int o = 4; o > 0; o >>= 1)
            v += __shfl_down_sync(0xFFFFFFFFu, v, o);
        if (lane == 0) {
            atomicAdd(&g_acc, (double)v);
            __threadfence();
            unsigned int t = atomicAdd(&g_ticket, 1u);
            s_last = (t == GRID2_ - 1);
        }
    }
    __syncthreads();

    if (s_last && threadIdx.x == 0) {
        __threadfence();
        out[0] = (float)(g_acc * (1.0 / ((double)LQ_ * (double)LD_)));
    }
}

extern "C" void kernel_launch(void* const* d_in, const int* in_sizes, int n_in,
                              void* d_out, int out_size) {
    const float*         questions = (const float*)d_in[0];
    const float*         docs      = (const float*)d_in[1];
    const unsigned char* is_ans    = (const unsigned char*)d_in[2];
    float* out = (float*)d_out;
    (void)in_sizes; (void)n_in; (void)out_size;

    prep_kernel<<<(B_ * D_ + 255) / 256, 256>>>(questions, is_ans);
    docs_reduce_kernel<<<GRID2_, BLK2_>>>((const float4*)docs, out);
}

// round 6
// speedup vs baseline: 1.3290x; 1.0950x over previous
#include <cuda_runtime.h>
#include <cuda_bf16.h>

// Shapes (fixed by the problem)
#define B_  32
#define N_  8
#define LQ_ 256
#define LD_ 512
#define D_  768

#define D4_         (D_ / 4)            // 192 float4 per row
#define BN_STRIDE4_ (LD_ * D4_)         // float4 per (b,n) slab = 98304

// Docs kernel geometry: 4 blocks per (b,n) slab, 128 rows each, BLK = D4_
#define BLKS_PER_SLAB_ 4
#define ROWS_PER_BLK_  (LD_ / BLKS_PER_SLAB_)   // 128
#define GRID_D_        (B_ * N_ * BLKS_PER_SLAB_) // 1024
#define BLK_D_         D4_                       // 192 threads

// Prep geometry: block = (b, chunk); 8 chunks of 32 rows over Lq=256
#define NCHUNK_ 8
#define CROWS_  (LQ_ / NCHUNK_)          // 32

// Scratch (no cudaMalloc allowed)
__device__ float  g_qpart[NCHUNK_][B_][D_]; // per-chunk partial column sums
__device__ float  g_sign[B_ * N_];          // +1 / -1 per (b,n)
__device__ double g_acc;
__device__ unsigned int g_ticket;

// ---------------------------------------------------------------------------
// Prep: decode is_ans (block 0), partial qsum per (b, chunk), reset acc/ticket.
// Partials are written to disjoint slabs -> no atomics, replay-safe.
// is_ans dtype sniffed (int32 / float32 / uint8) from first 256 bytes, which
// are in-bounds under every candidate encoding.
// ---------------------------------------------------------------------------
__global__ void __launch_bounds__(256) prep_kernel(
        const float* __restrict__ q, const unsigned char* __restrict__ isa) {
    if (blockIdx.x == 0) {
        __shared__ int enc;   // 0 = int32, 1 = float32, 2 = uint8
        if (threadIdx.x == 0) {
            const unsigned int* w = (const unsigned int*)isa;
            bool all01 = true, allf = true;
            for (int i = 0; i < (B_ * N_) / 4; ++i) {   // 64 words = 256 B
                unsigned int v = w[i];
                if (v != 0u && v != 1u)           all01 = false;
                if (v != 0u && v != 0x3F800000u)  allf  = false;
            }
            enc = all01 ? 0 : (allf ? 1 : 2);
            g_acc = 0.0;
            g_ticket = 0u;
        }
        __syncthreads();
        int i = threadIdx.x;                 // 0 .. 255
        bool ans;
        if (enc == 0)      ans = ((const int*)isa)[i]   != 0;
        else if (enc == 1) ans = ((const float*)isa)[i] != 0.0f;
        else               ans = isa[i]                 != 0;
        g_sign[i] = ans ? -1.0f : 1.0f;
    }

    int b = blockIdx.x >> 3;          // 0..31
    int c = blockIdx.x & 7;           // 0..7
    int t = threadIdx.x;              // 0..255; covers d = t, t+256, t+512
    const float* base = q + ((size_t)b * LQ_ + (size_t)c * CROWS_) * D_;

    float s0 = 0.f, s1 = 0.f, s2 = 0.f;
#pragma unroll 8
    for (int l = 0; l < CROWS_; ++l) {
        const float* r = base + (size_t)l * D_;
        s0 += r[t];
        s1 += r[t + 256];
        s2 += r[t + 512];
    }
    g_qpart[c][b][t]       = s0;
    g_qpart[c][b][t + 256] = s1;
    g_qpart[c][b][t + 512] = s2;
}

// ---------------------------------------------------------------------------
// Docs: column-stationary streaming reduce. threadIdx.x == d4 (fixed), so the
// per-thread qsum*sign float4 lives in registers; hot loop is pure
// ldcs + fma + pointer add. Last block (ticket) finalizes the scalar.
// ---------------------------------------------------------------------------
__global__ void __launch_bounds__(BLK_D_) docs_reduce_kernel(
        const float4* __restrict__ docs, float* __restrict__ out) {
    const int bn   = blockIdx.x >> 2;                 // 0..255
    const int b    = bn >> 3;
    const int d4   = threadIdx.x;                     // 0..191
    const int row0 = (blockIdx.x & 3) * ROWS_PER_BLK_;

    // Fold the 8 prep partials + sign into a register float4
    float4 qs = make_float4(0.f, 0.f, 0.f, 0.f);
#pragma unroll
    for (int c = 0; c < NCHUNK_; ++c) {
        const float* pp = &g_qpart[c][b][d4 * 4];
        qs.x += pp[0]; qs.y += pp[1]; qs.z += pp[2]; qs.w += pp[3];
    }
    {
        float s = g_sign[bn];
        qs.x *= s; qs.y *= s; qs.z *= s; qs.w *= s;
    }

    const float4* p = docs + (size_t)bn * BN_STRIDE4_
                           + (size_t)row0 * D4_ + d4;

    float4 a0 = make_float4(0.f, 0.f, 0.f, 0.f);
    float4 a1 = make_float4(0.f, 0.f, 0.f, 0.f);
#pragma unroll 4
    for (int m = 0; m < ROWS_PER_BLK_; m += 4) {
        float4 v0 = __ldcs(p);
        float4 v1 = __ldcs(p + D4_);
        float4 v2 = __ldcs(p + 2 * D4_);
        float4 v3 = __ldcs(p + 3 * D4_);
        p += 4 * D4_;
        a0.x = fmaf(v0.x, qs.x, a0.x); a0.y = fmaf(v0.y, qs.y, a0.y);
        a0.z = fmaf(v0.z, qs.z, a0.z); a0.w = fmaf(v0.w, qs.w, a0.w);
        a1.x = fmaf(v1.x, qs.x, a1.x); a1.y = fmaf(v1.y, qs.y, a1.y);
        a1.z = fmaf(v1.z, qs.z, a1.z); a1.w = fmaf(v1.w, qs.w, a1.w);
        a0.x = fmaf(v2.x, qs.x, a0.x); a0.y = fmaf(v2.y, qs.y, a0.y);
        a0.z = fmaf(v2.z, qs.z, a0.z); a0.w = fmaf(v2.w, qs.w, a0.w);
        a1.x = fmaf(v3.x, qs.x, a1.x); a1.y = fmaf(v3.y, qs.y, a1.y);
        a1.z = fmaf(v3.z, qs.z, a1.z); a1.w = fmaf(v3.w, qs.w, a1.w);
    }
    float acc = (a0.x + a0.y) + (a0.z + a0.w)
              + (a1.x + a1.y) + (a1.z + a1.w);

    // warp reduce (6 warps per block)
#pragma unroll
    for (int o = 16; o > 0; o >>= 1)
        acc += __shfl_down_sync(0xFFFFFFFFu, acc, o);

    __shared__ float warp_sums[BLK_D_ / 32];
    int lane = threadIdx.x & 31;
    int wid  = threadIdx.x >> 5;
    if (lane == 0) warp_sums[wid] = acc;
    __syncthreads();

    __shared__ bool s_last;
    if (threadIdx.x == 0) {
        float v = warp_sums[0];
#pragma unroll
        for (int w = 1; w < BLK_D_ / 32; ++w) v += warp_sums[w];
        atomicAdd(&g_acc, (double)v);
        __threadfence();
        unsigned int t = atomicAdd(&g_ticket, 1u);
        s_last = (t == GRID_D_ - 1);
    }
    __syncthreads();

    if (s_last && threadIdx.x == 0) {
        __threadfence();
        out[0] = (float)(g_acc * (1.0 / ((double)LQ_ * (double)LD_)));
    }
}

extern "C" void kernel_launch(void* const* d_in, const int* in_sizes, int n_in,
                              void* d_out, int out_size) {
    const float*         questions = (const float*)d_in[0];
    const float*         docs      = (const float*)d_in[1];
    const unsigned char* is_ans    = (const unsigned char*)d_in[2];
    float* out = (float*)d_out;
    (void)in_sizes; (void)n_in; (void)out_size;

    prep_kernel<<<B_ * NCHUNK_, 256>>>(questions, is_ans);
    docs_reduce_kernel<<<GRID_D_, BLK_D_>>>((const float4*)docs, out);
}